// round 13
// baseline (speedup 1.0000x reference)
#include <cuda_runtime.h>
#include <cstdint>
#include <cstddef>

#define HD 1024
#define BB 32
#define SS 2048
#define VV 32000
#define G3 3072
#define SC 16            // attention rows per chunk (smem-staged)
#define NCH (SS/SC)      // 128
#define SK 16            // k-split for GRU/q GEMMs
#define SKL 4            // logits k-split
#define KT 64            // GEMM k-tile

// X scratch is 64-k-blocked: X[kt][b][kk]  (kt = k>>6, kk = k&63)
#define XBLK(pos, b) (((size_t)((pos) >> 6)) * (BB * 64) + (size_t)(b) * 64 + ((pos) & 63))

// ---------------- scratch ----------------
__device__ __align__(256) float g_xT[2*HD*BB];
__device__ __align__(256) float g_hT[2*HD*BB];
__device__ __align__(256) float g_h0T[HD*BB];
__device__ __align__(256) float g_h1[BB*HD];
__device__ __align__(256) float g_h1T[HD*BB];
__device__ __align__(256) float g_catT[2*HD*BB];
__device__ __align__(256) float g_pgi[SK*BB*G3];
__device__ __align__(256) float g_pgh[SK*BB*G3];
__device__ __align__(256) float g_pq[SK*BB*HD];
__device__ __align__(256) float g_q[BB*HD];
__device__ float g_cb[BB];
__device__ __align__(256) float g_scores[BB*SS];
__device__ float g_pm[BB*NCH];
__device__ float g_pl[BB*NCH];
__device__ float g_wc[BB*NCH];
__device__ __align__(256) float g_pctx[(size_t)BB*NCH*HD];
__device__ float g_MZ[BB*2];
__device__ __align__(256) float g_plog[(size_t)SKL*BB*VV];
__device__ __align__(256) float g_logits[BB*VV];
__device__ float g_plm[BB*8];
__device__ float g_pls[BB*8];
__device__ float g_MZl[BB*2];

// ---------------- cp.async helpers ----------------
#define CPA_CG(dst, src) asm volatile("cp.async.cg.shared.global [%0], [%1], 16;" :: "r"(dst), "l"(src))
#define CPA_COMMIT() asm volatile("cp.async.commit_group;" ::: "memory")
#define CPA_WAIT1() asm volatile("cp.async.wait_group 1;" ::: "memory")
#define CPA_WAIT0() asm volatile("cp.async.wait_group 0;" ::: "memory")

// ---------------- reductions ----------------
__device__ __forceinline__ float blockReduceSum256(float v) {
    __shared__ float s[8];
    int lane = threadIdx.x & 31, w = threadIdx.x >> 5;
    __syncthreads();
    #pragma unroll
    for (int o = 16; o > 0; o >>= 1) v += __shfl_xor_sync(0xffffffffu, v, o);
    if (lane == 0) s[w] = v;
    __syncthreads();
    if (w == 0) {
        float x = (lane < 8) ? s[lane] : 0.0f;
        #pragma unroll
        for (int o = 4; o > 0; o >>= 1) x += __shfl_xor_sync(0xffffffffu, x, o);
        if (lane == 0) s[0] = x;
    }
    __syncthreads();
    return s[0];
}

// ---------------- 1: embedding + concat -> xT (blocked) ----------------
__global__ void k_embed(const int* __restrict__ ids, const float* __restrict__ emb,
                        const float* __restrict__ lastctx) {
    int b = blockIdx.x, t = threadIdx.x;
    float4 e = ((const float4*)(emb + (size_t)ids[b] * HD))[t];
    float4 c = ((const float4*)(lastctx + (size_t)b * HD))[t];
    int h = t * 4;
    g_xT[XBLK(h+0, b)] = e.x; g_xT[XBLK(h+1, b)] = e.y;
    g_xT[XBLK(h+2, b)] = e.z; g_xT[XBLK(h+3, b)] = e.w;
    g_xT[XBLK(HD+h+0, b)] = c.x; g_xT[XBLK(HD+h+1, b)] = c.y;
    g_xT[XBLK(HD+h+2, b)] = c.z; g_xT[XBLK(HD+h+3, b)] = c.w;
}

// ---------------- 2: transpose hidden [L,B,H] -> blocked [L][kt][b][64] ----------------
__global__ void k_transpose(const float* __restrict__ in) {
    __shared__ float s[32][33];
    int l = blockIdx.y, h0 = blockIdx.x * 32;
    int tx = threadIdx.x, ty = threadIdx.y;
    s[ty][tx] = in[(size_t)l * BB * HD + (size_t)ty * HD + h0 + tx];
    __syncthreads();
    int h = h0 + ty;
    g_hT[(size_t)l * HD * BB + XBLK(h, tx)] = s[tx][ty];
}

// ---------------- 3a: ASYNC skinny GEMM (cp.async double-buffered), wt==0 only ----------------
// C[b,n] = sum_k X[k][b] * W[n][k];  X blocked [kt][32][64], W row-major [N][Kt].
// dual problem via blockIdx.z; partial slot = blockIdx.y; bias at slot 0.
#define XS_F 2176          // 32*68 floats
#define WS_F 8192          // 128*64 floats
#define STG_F (XS_F + WS_F)
__global__ __launch_bounds__(128) void k_gemmA(
    const float* __restrict__ XT0, const float* __restrict__ W0, float* __restrict__ C0, int kchunk0, int Kt0,
    const float* __restrict__ XT1, const float* __restrict__ W1, float* __restrict__ C1, int kchunk1, int Kt1,
    const float* __restrict__ bias, int N)
{
    extern __shared__ float ds[];
    const float* XT = (blockIdx.z == 0) ? XT0 : XT1;
    const float* W  = (blockIdx.z == 0) ? W0  : W1;
    float* C        = (blockIdx.z == 0) ? C0  : C1;
    int kchunk      = (blockIdx.z == 0) ? kchunk0 : kchunk1;
    int K           = (blockIdx.z == 0) ? Kt0 : Kt1;

    int tid = threadIdx.x;
    int tn = tid & 15;
    int tb = tid >> 4;
    int n0 = blockIdx.x * 128;
    int kb = blockIdx.y * kchunk;
    int T = kchunk / KT;
    uint32_t sbase = (uint32_t)__cvta_generic_to_shared(ds);

    auto fill = [&](int s, int k0) {
        uint32_t xsa = sbase + (uint32_t)(s * STG_F) * 4u;
        uint32_t wsa = xsa + (uint32_t)XS_F * 4u;
        const float* xsrc = XT + (size_t)(k0 >> 6) * (BB * 64);
        #pragma unroll
        for (int r = 0; r < 4; r++) {
            int i4 = r * 128 + tid;
            int b = i4 >> 4, c = i4 & 15;
            CPA_CG(xsa + (uint32_t)(b * 68 + c * 4) * 4u,
                   (const void*)(xsrc + b * 64 + c * 4));
        }
        #pragma unroll
        for (int r = 0; r < 16; r++) {
            int i = r * 128 + tid;
            int n = i >> 4, c = i & 15;
            int cs = c ^ ((n >> 3) & 15);
            CPA_CG(wsa + (uint32_t)(n * 64 + cs * 4) * 4u,
                   (const void*)(W + (size_t)(n0 + n) * K + k0 + c * 4));
        }
        CPA_COMMIT();
    };

    unsigned long long acc[4][8];
    #pragma unroll
    for (int bi = 0; bi < 4; bi++)
        #pragma unroll
        for (int j = 0; j < 8; j++) acc[bi][j] = 0ull;

    fill(0, kb);
    for (int it = 0; it < T; it++) {
        if (it + 1 < T) { fill((it + 1) & 1, kb + (it + 1) * KT); CPA_WAIT1(); }
        else            { CPA_WAIT0(); }
        __syncthreads();
        float* Xs = ds + (it & 1) * STG_F;
        float* Ws = Xs + XS_F;
        #pragma unroll 4
        for (int kk = 0; kk < KT; kk += 4) {
            int csw = ((kk >> 2) ^ tn) * 4;
            unsigned long long x01[4], x23[4];
            #pragma unroll
            for (int bi = 0; bi < 4; bi++) {
                const float* xp = &Xs[(tb * 4 + bi) * 68 + kk];
                x01[bi] = *(const unsigned long long*)(xp);
                x23[bi] = *(const unsigned long long*)(xp + 2);
            }
            #pragma unroll
            for (int j = 0; j < 8; j++) {
                ulonglong2 w = *(const ulonglong2*)&Ws[(tn * 8 + j) * 64 + csw];
                #pragma unroll
                for (int bi = 0; bi < 4; bi++)
                    asm("fma.rn.f32x2 %0, %1, %2, %0;" : "+l"(acc[bi][j]) : "l"(x01[bi]), "l"(w.x));
                #pragma unroll
                for (int bi = 0; bi < 4; bi++)
                    asm("fma.rn.f32x2 %0, %1, %2, %0;" : "+l"(acc[bi][j]) : "l"(x23[bi]), "l"(w.y));
            }
        }
        __syncthreads();
    }

    size_t cbase = (size_t)blockIdx.y * BB * N;
    float v[4][8];
    #pragma unroll
    for (int j = 0; j < 8; j++) {
        float bv = (bias != nullptr && blockIdx.y == 0) ? bias[n0 + tn * 8 + j] : 0.0f;
        #pragma unroll
        for (int bi = 0; bi < 4; bi++) {
            float lo, hi;
            asm("mov.b64 {%0, %1}, %2;" : "=f"(lo), "=f"(hi) : "l"(acc[bi][j]));
            v[bi][j] = lo + hi + bv;
        }
    }
    #pragma unroll
    for (int bi = 0; bi < 4; bi++) {
        size_t off = cbase + (size_t)(tb * 4 + bi) * N + n0 + tn * 8;
        *(float4*)(C + off)     = make_float4(v[bi][0], v[bi][1], v[bi][2], v[bi][3]);
        *(float4*)(C + off + 4) = make_float4(v[bi][4], v[bi][5], v[bi][6], v[bi][7]);
    }
}

// ---------------- 3b: sync GEMM for wt==1 (q GEMM; W(n,k)=W[k*N+n]) ----------------
__global__ __launch_bounds__(128) void k_gemm(
    const float* __restrict__ XT, const float* __restrict__ W, float* __restrict__ C,
    int kchunk, int K, int N)
{
    __shared__ float Xs[32*68];
    __shared__ float Ws[128*64];
    int tid = threadIdx.x;
    int tn = tid & 15;
    int tb = tid >> 4;
    int n0 = blockIdx.x * 128;
    int kb = blockIdx.y * kchunk;

    unsigned long long acc[4][8];
    #pragma unroll
    for (int bi = 0; bi < 4; bi++)
        #pragma unroll
        for (int j = 0; j < 8; j++) acc[bi][j] = 0ull;

    for (int k0 = kb; k0 < kb + kchunk; k0 += KT) {
        const float* xsrc = XT + (size_t)(k0 >> 6) * (BB * 64);
        #pragma unroll
        for (int r = 0; r < 4; r++) {
            int i4 = r * 128 + tid;
            int b = i4 >> 4, c = i4 & 15;
            *(float4*)&Xs[b * 68 + c * 4] = *(const float4*)(xsrc + b * 64 + c * 4);
        }
        for (int i = tid; i < 128 * KT; i += 128) {
            int n = i & 127, k = i >> 7;
            int cs = (k >> 2) ^ ((n >> 3) & 15);
            Ws[n * 64 + cs * 4 + (k & 3)] = W[(size_t)(k0 + k) * N + n0 + n];
        }
        __syncthreads();
        #pragma unroll 4
        for (int kk = 0; kk < KT; kk += 4) {
            int csw = ((kk >> 2) ^ tn) * 4;
            unsigned long long x01[4], x23[4];
            #pragma unroll
            for (int bi = 0; bi < 4; bi++) {
                const float* xp = &Xs[(tb * 4 + bi) * 68 + kk];
                x01[bi] = *(const unsigned long long*)(xp);
                x23[bi] = *(const unsigned long long*)(xp + 2);
            }
            #pragma unroll
            for (int j = 0; j < 8; j++) {
                ulonglong2 w = *(const ulonglong2*)&Ws[(tn * 8 + j) * 64 + csw];
                #pragma unroll
                for (int bi = 0; bi < 4; bi++)
                    asm("fma.rn.f32x2 %0, %1, %2, %0;" : "+l"(acc[bi][j]) : "l"(x01[bi]), "l"(w.x));
                #pragma unroll
                for (int bi = 0; bi < 4; bi++)
                    asm("fma.rn.f32x2 %0, %1, %2, %0;" : "+l"(acc[bi][j]) : "l"(x23[bi]), "l"(w.y));
            }
        }
        __syncthreads();
    }

    size_t cbase = (size_t)blockIdx.y * BB * N;
    #pragma unroll
    for (int bi = 0; bi < 4; bi++) {
        float v[8];
        #pragma unroll
        for (int j = 0; j < 8; j++) {
            float lo, hi;
            asm("mov.b64 {%0, %1}, %2;" : "=f"(lo), "=f"(hi) : "l"(acc[bi][j]));
            v[j] = lo + hi;
        }
        size_t off = cbase + (size_t)(tb * 4 + bi) * N + n0 + tn * 8;
        *(float4*)(C + off)     = make_float4(v[0], v[1], v[2], v[3]);
        *(float4*)(C + off + 4) = make_float4(v[4], v[5], v[6], v[7]);
    }
}

// ---------------- 4: GRU gate combine (coalesced float4, block-half s-split) ----------------
// grid 64 x 256 threads. threads 0-127 reduce s in [0,8), threads 128-255 s in [8,16).
__global__ __launch_bounds__(256) void k_combine(
    const float* __restrict__ bih, const float* __restrict__ bhh,
    const float* __restrict__ hprev, float* __restrict__ houtT,
    float* __restrict__ hid_out, float* __restrict__ hout_row,
    float* __restrict__ catT)
{
    int t = threadIdx.x;
    int half = t >> 7;           // 0 or 1
    int i = t & 127;
    int f4 = blockIdx.x * 128 + i;      // 0..8191
    int b = f4 >> 8;                     // HD/4 = 256 f4 per batch
    int h = (f4 & 255) * 4;

    float4 gir = {0,0,0,0}, giz = {0,0,0,0}, gin = {0,0,0,0};
    float4 ghr = {0,0,0,0}, ghz = {0,0,0,0}, ghn = {0,0,0,0};
    int s0 = half * (SK / 2);
    #pragma unroll
    for (int s = 0; s < SK / 2; s++) {
        const float* pi = g_pgi + ((size_t)(s0 + s) * BB + b) * G3;
        const float* ph = g_pgh + ((size_t)(s0 + s) * BB + b) * G3;
        float4 v;
        v = *(const float4*)(pi + h);          gir.x += v.x; gir.y += v.y; gir.z += v.z; gir.w += v.w;
        v = *(const float4*)(pi + HD + h);     giz.x += v.x; giz.y += v.y; giz.z += v.z; giz.w += v.w;
        v = *(const float4*)(pi + 2*HD + h);   gin.x += v.x; gin.y += v.y; gin.z += v.z; gin.w += v.w;
        v = *(const float4*)(ph + h);          ghr.x += v.x; ghr.y += v.y; ghr.z += v.z; ghr.w += v.w;
        v = *(const float4*)(ph + HD + h);     ghz.x += v.x; ghz.y += v.y; ghz.z += v.z; ghz.w += v.w;
        v = *(const float4*)(ph + 2*HD + h);   ghn.x += v.x; ghn.y += v.y; ghn.z += v.z; ghn.w += v.w;
    }
    __shared__ float4 sx[6][128];
    if (half == 1) {
        sx[0][i] = gir; sx[1][i] = giz; sx[2][i] = gin;
        sx[3][i] = ghr; sx[4][i] = ghz; sx[5][i] = ghn;
    }
    __syncthreads();
    if (half == 0) {
        float4 v;
        v = sx[0][i]; gir.x += v.x; gir.y += v.y; gir.z += v.z; gir.w += v.w;
        v = sx[1][i]; giz.x += v.x; giz.y += v.y; giz.z += v.z; giz.w += v.w;
        v = sx[2][i]; gin.x += v.x; gin.y += v.y; gin.z += v.z; gin.w += v.w;
        v = sx[3][i]; ghr.x += v.x; ghr.y += v.y; ghr.z += v.z; ghr.w += v.w;
        v = sx[4][i]; ghz.x += v.x; ghz.y += v.y; ghz.z += v.z; ghz.w += v.w;
        v = sx[5][i]; ghn.x += v.x; ghn.y += v.y; ghn.z += v.z; ghn.w += v.w;
        float4 bir = *(const float4*)(bih + h);
        float4 biz = *(const float4*)(bih + HD + h);
        float4 bin = *(const float4*)(bih + 2*HD + h);
        float4 bhr = *(const float4*)(bhh + h);
        float4 bhz = *(const float4*)(bhh + HD + h);
        float4 bhn = *(const float4*)(bhh + 2*HD + h);
        float4 hp = *(const float4*)(hprev + (size_t)b * HD + h);
        float4 hn4;
        {
            float r = 1.0f / (1.0f + expf(-((gir.x + bir.x) + (ghr.x + bhr.x))));
            float z = 1.0f / (1.0f + expf(-((giz.x + biz.x) + (ghz.x + bhz.x))));
            float n = tanhf((gin.x + bin.x) + r * (ghn.x + bhn.x));
            hn4.x = (1.0f - z) * n + z * hp.x;
        }
        {
            float r = 1.0f / (1.0f + expf(-((gir.y + bir.y) + (ghr.y + bhr.y))));
            float z = 1.0f / (1.0f + expf(-((giz.y + biz.y) + (ghz.y + bhz.y))));
            float n = tanhf((gin.y + bin.y) + r * (ghn.y + bhn.y));
            hn4.y = (1.0f - z) * n + z * hp.y;
        }
        {
            float r = 1.0f / (1.0f + expf(-((gir.z + bir.z) + (ghr.z + bhr.z))));
            float z = 1.0f / (1.0f + expf(-((giz.z + biz.z) + (ghz.z + bhz.z))));
            float n = tanhf((gin.z + bin.z) + r * (ghn.z + bhn.z));
            hn4.z = (1.0f - z) * n + z * hp.z;
        }
        {
            float r = 1.0f / (1.0f + expf(-((gir.w + bir.w) + (ghr.w + bhr.w))));
            float z = 1.0f / (1.0f + expf(-((giz.w + biz.w) + (ghz.w + bhz.w))));
            float n = tanhf((gin.w + bin.w) + r * (ghn.w + bhn.w));
            hn4.w = (1.0f - z) * n + z * hp.w;
        }
        *(float4*)(houtT + XBLK(h, b)) = hn4;
        *(float4*)(hid_out + (size_t)b * HD + h) = hn4;
        if (hout_row) *(float4*)(hout_row + (size_t)b * HD + h) = hn4;
        if (catT) *(float4*)(catT + XBLK(h, b)) = hn4;
    }
}

// ---------------- 5: finalize q partials + cb = b_attn . h1 ----------------
__global__ void k_qfin(const float* __restrict__ b_attn) {
    int b = blockIdx.x, t = threadIdx.x;
    float4 acc = {0, 0, 0, 0};
    #pragma unroll
    for (int s = 0; s < SK; s++) {
        float4 v = *(const float4*)(g_pq + ((size_t)s * BB + b) * HD + t * 4);
        acc.x += v.x; acc.y += v.y; acc.z += v.z; acc.w += v.w;
    }
    *(float4*)(g_q + (size_t)b * HD + t * 4) = acc;
    float4 ba = *(const float4*)(b_attn + t * 4);
    float4 hv = *(const float4*)(g_h1 + (size_t)b * HD + t * 4);
    float p = ba.x * hv.x + ba.y * hv.y + ba.z * hv.z + ba.w * hv.w;
    p = blockReduceSum256(p);
    if (t == 0) g_cb[b] = p;
}

// ---------------- 6: attention chunk: smem-staged scores + partial ctx ----------------
__global__ __launch_bounds__(256) void k_scores_ctx(const float* __restrict__ enc) {
    extern __shared__ float sm[];
    float* qs = sm;
    float* es = sm + 1024;
    float* ps = sm + 1024 + 16 * 1028;
    int b = blockIdx.y, ch = blockIdx.x;
    int s0 = ch * SC;
    int t = threadIdx.x;
    ((float4*)qs)[t] = ((const float4*)(g_q + (size_t)b * HD))[t];
    const float4* eb = (const float4*)(enc + ((size_t)b * SS + s0) * HD);
    #pragma unroll
    for (int r = 0; r < 16; r++) {
        int i = r * 256 + t;
        int row = i >> 8, col = i & 255;
        ((float4*)es)[row * 257 + col] = eb[i];
    }
    __syncthreads();
    int w = t >> 5, lane = t & 31;
    float cb = g_cb[b];
    unsigned long long qr[16];
    #pragma unroll
    for (int i = 0; i < 8; i++) {
        ulonglong2 qq = *(const ulonglong2*)&qs[(lane + i * 32) * 4];
        qr[2 * i] = qq.x; qr[2 * i + 1] = qq.y;
    }
    #pragma unroll
    for (int rr = 0; rr < 2; rr++) {
        int r = w * 2 + rr;
        const float* e = es + r * 1028;
        unsigned long long a0 = 0ull, a1 = 0ull;
        #pragma unroll
        for (int i = 0; i < 8; i++) {
            ulonglong2 ee = *(const ulonglong2*)&e[(lane + i * 32) * 4];
            asm("fma.rn.f32x2 %0, %1, %2, %0;" : "+l"(a0) : "l"(ee.x), "l"(qr[2 * i]));
            asm("fma.rn.f32x2 %0, %1, %2, %0;" : "+l"(a1) : "l"(ee.y), "l"(qr[2 * i + 1]));
        }
        float l0, h0_, l1, h1_;
        asm("mov.b64 {%0, %1}, %2;" : "=f"(l0), "=f"(h0_) : "l"(a0));
        asm("mov.b64 {%0, %1}, %2;" : "=f"(l1), "=f"(h1_) : "l"(a1));
        float sum = (l0 + h0_) + (l1 + h1_);
        #pragma unroll
        for (int o = 16; o > 0; o >>= 1) sum += __shfl_xor_sync(0xffffffffu, sum, o);
        if (lane == 0) {
            float val = sum + cb;
            ps[r] = val;
            g_scores[(size_t)b * SS + s0 + r] = val;
        }
    }
    __syncthreads();
    if (t < 32) {
        float v = (t < SC) ? ps[t] : -3.0e38f;
        float m = v;
        #pragma unroll
        for (int o = 16; o > 0; o >>= 1) m = fmaxf(m, __shfl_xor_sync(0xffffffffu, m, o));
        float p = (t < SC) ? expf(v - m) : 0.0f;
        float l = p;
        #pragma unroll
        for (int o = 16; o > 0; o >>= 1) l += __shfl_xor_sync(0xffffffffu, l, o);
        if (t < SC) ps[t] = p;
        if (t == 0) { g_pm[b * NCH + ch] = m; g_pl[b * NCH + ch] = l; }
    }
    __syncthreads();
    float4 acc = {0, 0, 0, 0};
    #pragma unroll
    for (int s = 0; s < SC; s++) {
        float p = ps[s];
        float4 ev = ((const float4*)es)[s * 257 + t];
        acc.x += p * ev.x; acc.y += p * ev.y; acc.z += p * ev.z; acc.w += p * ev.w;
    }
    *(float4*)(g_pctx + ((size_t)(b * NCH + ch)) * HD + t * 4) = acc;
}

// ---------------- 7: global attn stats + chunk weights ----------------
__global__ void k_astat() {
    int b = blockIdx.x, t = threadIdx.x;   // NCH threads
    float m = g_pm[b * NCH + t];
    float l = g_pl[b * NCH + t];
    int lane = t & 31, w = t >> 5;
    float mm = m, ll = l;
    #pragma unroll
    for (int o = 16; o > 0; o >>= 1) {
        float mo = __shfl_xor_sync(0xffffffffu, mm, o);
        float lo = __shfl_xor_sync(0xffffffffu, ll, o);
        float M = fmaxf(mm, mo);
        ll = ll * expf(mm - M) + lo * expf(mo - M);
        mm = M;
    }
    __shared__ float sm_[4], sl_[4], MZ[2];
    if (lane == 0) { sm_[w] = mm; sl_[w] = ll; }
    __syncthreads();
    if (t == 0) {
        float M = sm_[0], Z = sl_[0];
        #pragma unroll
        for (int i = 1; i < 4; i++) {
            float M2 = fmaxf(M, sm_[i]);
            Z = Z * expf(M - M2) + sl_[i] * expf(sm_[i] - M2);
            M = M2;
        }
        MZ[0] = M; MZ[1] = Z;
        g_MZ[b * 2] = M; g_MZ[b * 2 + 1] = Z;
    }
    __syncthreads();
    g_wc[b * NCH + t] = expf(m - MZ[0]) / MZ[1];
}

// ---------------- 8: context reduce -> ctx_out + catT (blocked) ----------------
__global__ __launch_bounds__(256) void k_act(float* __restrict__ ctx_out) {
    int b = blockIdx.x, g = blockIdx.y;
    int t = threadIdx.x;
    int cg = t >> 5, i = t & 31;
    int f4c = g * 32 + i;
    __shared__ float wcs[NCH];
    if (t < NCH) wcs[t] = g_wc[b * NCH + t];
    __syncthreads();
    float4 acc = {0, 0, 0, 0};
    #pragma unroll
    for (int c = cg; c < NCH; c += 8) {
        float s = wcs[c];
        float4 v = *(const float4*)(g_pctx + ((size_t)(b * NCH + c)) * HD + f4c * 4);
        acc.x += s * v.x; acc.y += s * v.y; acc.z += s * v.z; acc.w += s * v.w;
    }
    __shared__ float4 red[8][32];
    red[cg][i] = acc;
    __syncthreads();
    if (cg == 0) {
        #pragma unroll
        for (int r = 1; r < 8; r++) {
            float4 v = red[r][i];
            acc.x += v.x; acc.y += v.y; acc.z += v.z; acc.w += v.w;
        }
        int h = f4c * 4;
        *(float4*)(ctx_out + (size_t)b * HD + h) = acc;
        g_catT[XBLK(HD + h + 0, b)] = acc.x;
        g_catT[XBLK(HD + h + 1, b)] = acc.y;
        g_catT[XBLK(HD + h + 2, b)] = acc.z;
        g_catT[XBLK(HD + h + 3, b)] = acc.w;
    }
}

// ---------------- 9: normalized attention weights ----------------
__global__ void k_attn_out(float* __restrict__ attn_out) {
    int idx = blockIdx.x * 256 + threadIdx.x;
    int b = idx >> 11;
    float M = g_MZ[b * 2], Z = g_MZ[b * 2 + 1];
    attn_out[idx] = expf(g_scores[idx] - M) / Z;
}

// ---------------- 10: combine logits partials + per-block softmax stats ----------------
__global__ __launch_bounds__(256) void k_lcombine() {
    int b = blockIdx.x, y = blockIdx.y;       // 8 segments of 1000 float4 per batch
    int t = threadIdx.x;
    size_t base4 = (size_t)b * (VV / 4) + (size_t)y * 1000;
    float m = -3.0e38f, s = 0.0f;
    for (int i = t; i < 1000; i += 256) {
        size_t i4 = base4 + i;
        float4 a = *(const float4*)(g_plog + i4 * 4);
        #pragma unroll
        for (int sk = 1; sk < SKL; sk++) {
            float4 v = *(const float4*)(g_plog + (size_t)sk * BB * VV + i4 * 4);
            a.x += v.x; a.y += v.y; a.z += v.z; a.w += v.w;
        }
        *(float4*)(g_logits + i4 * 4) = a;
        float m2 = fmaxf(fmaxf(a.x, a.y), fmaxf(a.z, a.w));
        if (m2 <= m) {
            s += expf(a.x - m) + expf(a.y - m) + expf(a.z - m) + expf(a.w - m);
        } else {
            s = s * expf(m - m2) + expf(a.x - m2) + expf(a.y - m2) + expf(a.z - m2) + expf(a.w - m2);
            m = m2;
        }
    }
    int lane = t & 31, w = t >> 5;
    #pragma unroll
    for (int o = 16; o > 0; o >>= 1) {
        float mo = __shfl_xor_sync(0xffffffffu, m, o);
        float so = __shfl_xor_sync(0xffffffffu, s, o);
        float M = fmaxf(m, mo);
        s = s * expf(m - M) + so * expf(mo - M);
        m = M;
    }
    __shared__ float sm_[8], ss_[8];
    if (lane == 0) { sm_[w] = m; ss_[w] = s; }
    __syncthreads();
    if (t == 0) {
        float M = sm_[0], S = ss_[0];
        #pragma unroll
        for (int i = 1; i < 8; i++) {
            float M2 = fmaxf(M, sm_[i]);
            S = S * expf(M - M2) + ss_[i] * expf(sm_[i] - M2);
            M = M2;
        }
        g_plm[b * 8 + y] = M; g_pls[b * 8 + y] = S;
    }
}

// ---------------- 11: tiny final logits stats ----------------
__global__ void k_lstat2() {
    int b = blockIdx.x, t = threadIdx.x;   // 32 threads
    float m = (t < 8) ? g_plm[b * 8 + t] : -3.0e38f;
    float s = (t < 8) ? g_pls[b * 8 + t] : 0.0f;
    #pragma unroll
    for (int o = 4; o > 0; o >>= 1) {
        float mo = __shfl_xor_sync(0xffffffffu, m, o);
        float so = __shfl_xor_sync(0xffffffffu, s, o);
        float M = fmaxf(m, mo);
        s = s * expf(m - M) + so * expf(mo - M);
        m = M;
    }
    if (t == 0) { g_MZl[b * 2] = m; g_MZl[b * 2 + 1] = s; }
}

// ---------------- 12: write output softmax ----------------
__global__ void k_wout(float* __restrict__ out) {
    int i4 = blockIdx.x * 256 + threadIdx.x;
    int idx = i4 * 4;
    int b = idx / VV;
    float M = g_MZl[b * 2];
    float invZ = 1.0f / g_MZl[b * 2 + 1];
    float4 l = *(const float4*)(g_logits + idx);
    float4 o;
    o.x = expf(l.x - M) * invZ; o.y = expf(l.y - M) * invZ;
    o.z = expf(l.z - M) * invZ; o.w = expf(l.w - M) * invZ;
    *(float4*)(out + idx) = o;
}

// ---------------- launch ----------------
extern "C" void kernel_launch(void* const* d_in, const int* in_sizes, int n_in,
                              void* d_out, int out_size) {
    const int*   ids   = (const int*)d_in[0];
    const float* lctx  = (const float*)d_in[1];
    const float* hid   = (const float*)d_in[2];
    const float* enc   = (const float*)d_in[3];
    const float* emb   = (const float*)d_in[4];
    const float* Wattn = (const float*)d_in[5];
    const float* battn = (const float*)d_in[6];
    const float* Wih0  = (const float*)d_in[7];
    const float* Whh0  = (const float*)d_in[8];
    const float* bih0  = (const float*)d_in[9];
    const float* bhh0  = (const float*)d_in[10];
    const float* Wih1  = (const float*)d_in[11];
    const float* Whh1  = (const float*)d_in[12];
    const float* bih1  = (const float*)d_in[13];
    const float* bhh1  = (const float*)d_in[14];
    const float* Wout  = (const float*)d_in[15];
    const float* bout  = (const float*)d_in[16];

    float* out = (float*)d_out;
    float* out_probs = out;
    float* out_ctx   = out + (size_t)BB * VV;
    float* out_hid   = out_ctx + (size_t)BB * HD;
    float* out_attn  = out_hid + (size_t)2 * BB * HD;

    float *p_xT, *p_hT, *p_h0T, *p_h1, *p_h1T, *p_catT, *p_pgi, *p_pgh, *p_pq, *p_plog;
    cudaGetSymbolAddress((void**)&p_xT,   g_xT);
    cudaGetSymbolAddress((void**)&p_hT,   g_hT);
    cudaGetSymbolAddress((void**)&p_h0T,  g_h0T);
    cudaGetSymbolAddress((void**)&p_h1,   g_h1);
    cudaGetSymbolAddress((void**)&p_h1T,  g_h1T);
    cudaGetSymbolAddress((void**)&p_catT, g_catT);
    cudaGetSymbolAddress((void**)&p_pgi,  g_pgi);
    cudaGetSymbolAddress((void**)&p_pgh,  g_pgh);
    cudaGetSymbolAddress((void**)&p_pq,   g_pq);
    cudaGetSymbolAddress((void**)&p_plog, g_plog);

    const int ATTN_SMEM  = (1024 + 16 * 1028 + 16) * 4;   // 69952 B
    const int GEMMA_SMEM = 2 * STG_F * 4;                 // 82944 B
    static int init_done = 0;
    if (!init_done) {
        cudaFuncSetAttribute(k_scores_ctx, cudaFuncAttributeMaxDynamicSharedMemorySize, ATTN_SMEM);
        cudaFuncSetAttribute(k_gemmA, cudaFuncAttributeMaxDynamicSharedMemorySize, GEMMA_SMEM);
        init_done = 1;
    }

    // 1. inputs -> blocked layouts
    k_embed<<<BB, 256>>>(ids, emb, lctx);
    k_transpose<<<dim3(HD / 32, 2), dim3(32, 32)>>>(hid);
    // 2. GRU layer 0 (async dual GEMM: z=0 Wih0/xT K=2048, z=1 Whh0/hT K=1024)
    k_gemmA<<<dim3(G3/128, SK, 2), 128, GEMMA_SMEM>>>(
        p_xT, Wih0, p_pgi, (2*HD)/SK, 2*HD,
        p_hT, Whh0, p_pgh, HD/SK, HD, nullptr, G3);
    k_combine<<<64, 256>>>(bih0, bhh0, hid, p_h0T, out_hid, nullptr, nullptr);
    // 3. GRU layer 1
    k_gemmA<<<dim3(G3/128, SK, 2), 128, GEMMA_SMEM>>>(
        p_h0T, Wih1, p_pgi, HD/SK, HD,
        p_hT + HD*BB, Whh1, p_pgh, HD/SK, HD, nullptr, G3);
    k_combine<<<64, 256>>>(bih1, bhh1, hid + BB*HD, p_h1T, out_hid + BB*HD, p_h1, p_catT);
    // 4. q = h1 @ W_attn (sync GEMM, transposed W)
    k_gemm<<<dim3(HD/128, SK), 128>>>(p_h1T, Wattn, p_pq, HD/SK, HD, HD);
    k_qfin<<<BB, 256>>>(battn);
    // 5. attention (single DRAM pass, smem-staged)
    k_scores_ctx<<<dim3(NCH, BB), 256, ATTN_SMEM>>>(enc);
    k_astat<<<BB, NCH>>>();
    k_act<<<dim3(BB, 8), 256>>>(out_ctx);
    k_attn_out<<<(BB*SS)/256, 256>>>(out_attn);
    // 6. logits GEMM (async, k-split x4) + fused-stat epilogue
    k_gemmA<<<dim3(VV/128, SKL, 1), 128, GEMMA_SMEM>>>(
        p_catT, Wout, p_plog, (2*HD)/SKL, 2*HD,
        p_catT, Wout, p_plog, (2*HD)/SKL, 2*HD, bout, VV);
    k_lcombine<<<dim3(BB, 8), 256>>>();
    k_lstat2<<<BB, 32>>>();
    k_wout<<<(BB*VV/4)/256, 256>>>(out_probs);
}

// round 14
// speedup vs baseline: 1.0214x; 1.0214x over previous
#include <cuda_runtime.h>
#include <cstdint>
#include <cstddef>

#define HD 1024
#define BB 32
#define SS 2048
#define VV 32000
#define G3 3072
#define SC 16            // attention rows per chunk (smem-staged)
#define NCH (SS/SC)      // 128
#define SK 16            // k-split for GRU/q GEMMs
#define SKL 4            // logits k-split
#define KT 64            // GEMM k-tile

// X scratch is 64-k-blocked: X[kt][b][kk]  (kt = k>>6, kk = k&63)
#define XBLK(pos, b) (((size_t)((pos) >> 6)) * (BB * 64) + (size_t)(b) * 64 + ((pos) & 63))

// ---------------- scratch ----------------
__device__ __align__(256) float g_xT[2*HD*BB];
__device__ __align__(256) float g_hT[2*HD*BB];
__device__ __align__(256) float g_h0T[HD*BB];
__device__ __align__(256) float g_h1[BB*HD];
__device__ __align__(256) float g_h1T[HD*BB];
__device__ __align__(256) float g_catT[2*HD*BB];
__device__ __align__(256) float g_pgi[SK*BB*G3];
__device__ __align__(256) float g_pgh[SK*BB*G3];
__device__ __align__(256) float g_pq[SK*BB*HD];
__device__ __align__(256) float g_q[BB*HD];
__device__ float g_cb[BB];
__device__ __align__(256) float g_scores[BB*SS];
__device__ float g_pm[BB*NCH];
__device__ float g_pl[BB*NCH];
__device__ __align__(256) float g_pctx[(size_t)BB*NCH*HD];
__device__ __align__(256) float g_plog[(size_t)SKL*BB*VV];
__device__ __align__(256) float g_logits[BB*VV];
__device__ float g_plm[BB*8];
__device__ float g_pls[BB*8];

// ---------------- cp.async helpers ----------------
#define CPA_CG(dst, src) asm volatile("cp.async.cg.shared.global [%0], [%1], 16;" :: "r"(dst), "l"(src))
#define CPA_COMMIT() asm volatile("cp.async.commit_group;" ::: "memory")
#define CPA_WAIT1() asm volatile("cp.async.wait_group 1;" ::: "memory")
#define CPA_WAIT0() asm volatile("cp.async.wait_group 0;" ::: "memory")

// ---------------- reductions ----------------
__device__ __forceinline__ float blockReduceSum256(float v) {
    __shared__ float s[8];
    int lane = threadIdx.x & 31, w = threadIdx.x >> 5;
    __syncthreads();
    #pragma unroll
    for (int o = 16; o > 0; o >>= 1) v += __shfl_xor_sync(0xffffffffu, v, o);
    if (lane == 0) s[w] = v;
    __syncthreads();
    if (w == 0) {
        float x = (lane < 8) ? s[lane] : 0.0f;
        #pragma unroll
        for (int o = 4; o > 0; o >>= 1) x += __shfl_xor_sync(0xffffffffu, x, o);
        if (lane == 0) s[0] = x;
    }
    __syncthreads();
    return s[0];
}

// ---------------- 1: embedding + concat -> xT (blocked) ----------------
__global__ void k_embed(const int* __restrict__ ids, const float* __restrict__ emb,
                        const float* __restrict__ lastctx) {
    int b = blockIdx.x, t = threadIdx.x;
    float4 e = ((const float4*)(emb + (size_t)ids[b] * HD))[t];
    float4 c = ((const float4*)(lastctx + (size_t)b * HD))[t];
    int h = t * 4;
    g_xT[XBLK(h+0, b)] = e.x; g_xT[XBLK(h+1, b)] = e.y;
    g_xT[XBLK(h+2, b)] = e.z; g_xT[XBLK(h+3, b)] = e.w;
    g_xT[XBLK(HD+h+0, b)] = c.x; g_xT[XBLK(HD+h+1, b)] = c.y;
    g_xT[XBLK(HD+h+2, b)] = c.z; g_xT[XBLK(HD+h+3, b)] = c.w;
}

// ---------------- 2: transpose hidden [L,B,H] -> blocked [L][kt][b][64] ----------------
__global__ void k_transpose(const float* __restrict__ in) {
    __shared__ float s[32][33];
    int l = blockIdx.y, h0 = blockIdx.x * 32;
    int tx = threadIdx.x, ty = threadIdx.y;
    s[ty][tx] = in[(size_t)l * BB * HD + (size_t)ty * HD + h0 + tx];
    __syncthreads();
    int h = h0 + ty;
    g_hT[(size_t)l * HD * BB + XBLK(h, tx)] = s[tx][ty];
}

// ---------------- 3a: ASYNC skinny GEMM (cp.async double-buffered), wt==0 only ----------------
#define XS_F 2176          // 32*68 floats
#define WS_F 8192          // 128*64 floats
#define STG_F (XS_F + WS_F)
__global__ __launch_bounds__(128) void k_gemmA(
    const float* __restrict__ XT0, const float* __restrict__ W0, float* __restrict__ C0, int kchunk0, int Kt0,
    const float* __restrict__ XT1, const float* __restrict__ W1, float* __restrict__ C1, int kchunk1, int Kt1,
    const float* __restrict__ bias, int N)
{
    extern __shared__ float ds[];
    const float* XT = (blockIdx.z == 0) ? XT0 : XT1;
    const float* W  = (blockIdx.z == 0) ? W0  : W1;
    float* C        = (blockIdx.z == 0) ? C0  : C1;
    int kchunk      = (blockIdx.z == 0) ? kchunk0 : kchunk1;
    int K           = (blockIdx.z == 0) ? Kt0 : Kt1;

    int tid = threadIdx.x;
    int tn = tid & 15;
    int tb = tid >> 4;
    int n0 = blockIdx.x * 128;
    int kb = blockIdx.y * kchunk;
    int T = kchunk / KT;
    uint32_t sbase = (uint32_t)__cvta_generic_to_shared(ds);

    auto fill = [&](int s, int k0) {
        uint32_t xsa = sbase + (uint32_t)(s * STG_F) * 4u;
        uint32_t wsa = xsa + (uint32_t)XS_F * 4u;
        const float* xsrc = XT + (size_t)(k0 >> 6) * (BB * 64);
        #pragma unroll
        for (int r = 0; r < 4; r++) {
            int i4 = r * 128 + tid;
            int b = i4 >> 4, c = i4 & 15;
            CPA_CG(xsa + (uint32_t)(b * 68 + c * 4) * 4u,
                   (const void*)(xsrc + b * 64 + c * 4));
        }
        #pragma unroll
        for (int r = 0; r < 16; r++) {
            int i = r * 128 + tid;
            int n = i >> 4, c = i & 15;
            int cs = c ^ ((n >> 3) & 15);
            CPA_CG(wsa + (uint32_t)(n * 64 + cs * 4) * 4u,
                   (const void*)(W + (size_t)(n0 + n) * K + k0 + c * 4));
        }
        CPA_COMMIT();
    };

    unsigned long long acc[4][8];
    #pragma unroll
    for (int bi = 0; bi < 4; bi++)
        #pragma unroll
        for (int j = 0; j < 8; j++) acc[bi][j] = 0ull;

    fill(0, kb);
    for (int it = 0; it < T; it++) {
        if (it + 1 < T) { fill((it + 1) & 1, kb + (it + 1) * KT); CPA_WAIT1(); }
        else            { CPA_WAIT0(); }
        __syncthreads();
        float* Xs = ds + (it & 1) * STG_F;
        float* Ws = Xs + XS_F;
        #pragma unroll 4
        for (int kk = 0; kk < KT; kk += 4) {
            int csw = ((kk >> 2) ^ tn) * 4;
            unsigned long long x01[4], x23[4];
            #pragma unroll
            for (int bi = 0; bi < 4; bi++) {
                const float* xp = &Xs[(tb * 4 + bi) * 68 + kk];
                x01[bi] = *(const unsigned long long*)(xp);
                x23[bi] = *(const unsigned long long*)(xp + 2);
            }
            #pragma unroll
            for (int j = 0; j < 8; j++) {
                ulonglong2 w = *(const ulonglong2*)&Ws[(tn * 8 + j) * 64 + csw];
                #pragma unroll
                for (int bi = 0; bi < 4; bi++)
                    asm("fma.rn.f32x2 %0, %1, %2, %0;" : "+l"(acc[bi][j]) : "l"(x01[bi]), "l"(w.x));
                #pragma unroll
                for (int bi = 0; bi < 4; bi++)
                    asm("fma.rn.f32x2 %0, %1, %2, %0;" : "+l"(acc[bi][j]) : "l"(x23[bi]), "l"(w.y));
            }
        }
        __syncthreads();
    }

    size_t cbase = (size_t)blockIdx.y * BB * N;
    float v[4][8];
    #pragma unroll
    for (int j = 0; j < 8; j++) {
        float bv = (bias != nullptr && blockIdx.y == 0) ? bias[n0 + tn * 8 + j] : 0.0f;
        #pragma unroll
        for (int bi = 0; bi < 4; bi++) {
            float lo, hi;
            asm("mov.b64 {%0, %1}, %2;" : "=f"(lo), "=f"(hi) : "l"(acc[bi][j]));
            v[bi][j] = lo + hi + bv;
        }
    }
    #pragma unroll
    for (int bi = 0; bi < 4; bi++) {
        size_t off = cbase + (size_t)(tb * 4 + bi) * N + n0 + tn * 8;
        *(float4*)(C + off)     = make_float4(v[bi][0], v[bi][1], v[bi][2], v[bi][3]);
        *(float4*)(C + off + 4) = make_float4(v[bi][4], v[bi][5], v[bi][6], v[bi][7]);
    }
}

// ---------------- 3b: sync GEMM for wt==1 (q GEMM; W(n,k)=W[k*N+n]) ----------------
__global__ __launch_bounds__(128) void k_gemm(
    const float* __restrict__ XT, const float* __restrict__ W, float* __restrict__ C,
    int kchunk, int K, int N)
{
    __shared__ float Xs[32*68];
    __shared__ float Ws[128*64];
    int tid = threadIdx.x;
    int tn = tid & 15;
    int tb = tid >> 4;
    int n0 = blockIdx.x * 128;
    int kb = blockIdx.y * kchunk;

    unsigned long long acc[4][8];
    #pragma unroll
    for (int bi = 0; bi < 4; bi++)
        #pragma unroll
        for (int j = 0; j < 8; j++) acc[bi][j] = 0ull;

    for (int k0 = kb; k0 < kb + kchunk; k0 += KT) {
        const float* xsrc = XT + (size_t)(k0 >> 6) * (BB * 64);
        #pragma unroll
        for (int r = 0; r < 4; r++) {
            int i4 = r * 128 + tid;
            int b = i4 >> 4, c = i4 & 15;
            *(float4*)&Xs[b * 68 + c * 4] = *(const float4*)(xsrc + b * 64 + c * 4);
        }
        for (int i = tid; i < 128 * KT; i += 128) {
            int n = i & 127, k = i >> 7;
            int cs = (k >> 2) ^ ((n >> 3) & 15);
            Ws[n * 64 + cs * 4 + (k & 3)] = W[(size_t)(k0 + k) * N + n0 + n];
        }
        __syncthreads();
        #pragma unroll 4
        for (int kk = 0; kk < KT; kk += 4) {
            int csw = ((kk >> 2) ^ tn) * 4;
            unsigned long long x01[4], x23[4];
            #pragma unroll
            for (int bi = 0; bi < 4; bi++) {
                const float* xp = &Xs[(tb * 4 + bi) * 68 + kk];
                x01[bi] = *(const unsigned long long*)(xp);
                x23[bi] = *(const unsigned long long*)(xp + 2);
            }
            #pragma unroll
            for (int j = 0; j < 8; j++) {
                ulonglong2 w = *(const ulonglong2*)&Ws[(tn * 8 + j) * 64 + csw];
                #pragma unroll
                for (int bi = 0; bi < 4; bi++)
                    asm("fma.rn.f32x2 %0, %1, %2, %0;" : "+l"(acc[bi][j]) : "l"(x01[bi]), "l"(w.x));
                #pragma unroll
                for (int bi = 0; bi < 4; bi++)
                    asm("fma.rn.f32x2 %0, %1, %2, %0;" : "+l"(acc[bi][j]) : "l"(x23[bi]), "l"(w.y));
            }
        }
        __syncthreads();
    }

    size_t cbase = (size_t)blockIdx.y * BB * N;
    #pragma unroll
    for (int bi = 0; bi < 4; bi++) {
        float v[8];
        #pragma unroll
        for (int j = 0; j < 8; j++) {
            float lo, hi;
            asm("mov.b64 {%0, %1}, %2;" : "=f"(lo), "=f"(hi) : "l"(acc[bi][j]));
            v[j] = lo + hi;
        }
        size_t off = cbase + (size_t)(tb * 4 + bi) * N + n0 + tn * 8;
        *(float4*)(C + off)     = make_float4(v[0], v[1], v[2], v[3]);
        *(float4*)(C + off + 4) = make_float4(v[4], v[5], v[6], v[7]);
    }
}

// ---------------- 4: GRU gate combine (coalesced float4 + s-split x8) ----------------
// grid 256 x 256 threads. warp w reduces s in [2w, 2w+2) for 32 contiguous f4.
__global__ __launch_bounds__(256) void k_combine(
    const float* __restrict__ bih, const float* __restrict__ bhh,
    const float* __restrict__ hprev, float* __restrict__ houtT,
    float* __restrict__ hid_out, float* __restrict__ hout_row,
    float* __restrict__ catT)
{
    int t = threadIdx.x;
    int sp = t >> 5, i = t & 31;
    int f4 = blockIdx.x * 32 + i;        // 0..8191
    int b = f4 >> 8;
    int h = (f4 & 255) * 4;

    float4 acc[6];
    #pragma unroll
    for (int j = 0; j < 6; j++) acc[j] = make_float4(0, 0, 0, 0);
    #pragma unroll
    for (int s = 0; s < 2; s++) {
        const float* pi = g_pgi + ((size_t)(sp * 2 + s) * BB + b) * G3;
        const float* ph = g_pgh + ((size_t)(sp * 2 + s) * BB + b) * G3;
        float4 v;
        v = *(const float4*)(pi + h);        acc[0].x+=v.x; acc[0].y+=v.y; acc[0].z+=v.z; acc[0].w+=v.w;
        v = *(const float4*)(pi + HD + h);   acc[1].x+=v.x; acc[1].y+=v.y; acc[1].z+=v.z; acc[1].w+=v.w;
        v = *(const float4*)(pi + 2*HD + h); acc[2].x+=v.x; acc[2].y+=v.y; acc[2].z+=v.z; acc[2].w+=v.w;
        v = *(const float4*)(ph + h);        acc[3].x+=v.x; acc[3].y+=v.y; acc[3].z+=v.z; acc[3].w+=v.w;
        v = *(const float4*)(ph + HD + h);   acc[4].x+=v.x; acc[4].y+=v.y; acc[4].z+=v.z; acc[4].w+=v.w;
        v = *(const float4*)(ph + 2*HD + h); acc[5].x+=v.x; acc[5].y+=v.y; acc[5].z+=v.z; acc[5].w+=v.w;
    }
    __shared__ float4 sx[6][8][32];
    if (sp > 0) {
        #pragma unroll
        for (int j = 0; j < 6; j++) sx[j][sp][i] = acc[j];
    }
    __syncthreads();
    if (sp == 0) {
        #pragma unroll
        for (int r = 1; r < 8; r++) {
            #pragma unroll
            for (int j = 0; j < 6; j++) {
                float4 v = sx[j][r][i];
                acc[j].x += v.x; acc[j].y += v.y; acc[j].z += v.z; acc[j].w += v.w;
            }
        }
        float4 bir = *(const float4*)(bih + h);
        float4 biz = *(const float4*)(bih + HD + h);
        float4 bin = *(const float4*)(bih + 2*HD + h);
        float4 bhr = *(const float4*)(bhh + h);
        float4 bhz = *(const float4*)(bhh + HD + h);
        float4 bhn = *(const float4*)(bhh + 2*HD + h);
        float4 hp = *(const float4*)(hprev + (size_t)b * HD + h);
        float4 hn4;
        {
            float r = 1.0f / (1.0f + expf(-((acc[0].x + bir.x) + (acc[3].x + bhr.x))));
            float z = 1.0f / (1.0f + expf(-((acc[1].x + biz.x) + (acc[4].x + bhz.x))));
            float n = tanhf((acc[2].x + bin.x) + r * (acc[5].x + bhn.x));
            hn4.x = (1.0f - z) * n + z * hp.x;
        }
        {
            float r = 1.0f / (1.0f + expf(-((acc[0].y + bir.y) + (acc[3].y + bhr.y))));
            float z = 1.0f / (1.0f + expf(-((acc[1].y + biz.y) + (acc[4].y + bhz.y))));
            float n = tanhf((acc[2].y + bin.y) + r * (acc[5].y + bhn.y));
            hn4.y = (1.0f - z) * n + z * hp.y;
        }
        {
            float r = 1.0f / (1.0f + expf(-((acc[0].z + bir.z) + (acc[3].z + bhr.z))));
            float z = 1.0f / (1.0f + expf(-((acc[1].z + biz.z) + (acc[4].z + bhz.z))));
            float n = tanhf((acc[2].z + bin.z) + r * (acc[5].z + bhn.z));
            hn4.z = (1.0f - z) * n + z * hp.z;
        }
        {
            float r = 1.0f / (1.0f + expf(-((acc[0].w + bir.w) + (acc[3].w + bhr.w))));
            float z = 1.0f / (1.0f + expf(-((acc[1].w + biz.w) + (acc[4].w + bhz.w))));
            float n = tanhf((acc[2].w + bin.w) + r * (acc[5].w + bhn.w));
            hn4.w = (1.0f - z) * n + z * hp.w;
        }
        *(float4*)(houtT + XBLK(h, b)) = hn4;
        *(float4*)(hid_out + (size_t)b * HD + h) = hn4;
        if (hout_row) *(float4*)(hout_row + (size_t)b * HD + h) = hn4;
        if (catT) *(float4*)(catT + XBLK(h, b)) = hn4;
    }
}

// ---------------- 5: finalize q partials + cb = b_attn . h1 ----------------
__global__ void k_qfin(const float* __restrict__ b_attn) {
    int b = blockIdx.x, t = threadIdx.x;
    float4 acc = {0, 0, 0, 0};
    #pragma unroll
    for (int s = 0; s < SK; s++) {
        float4 v = *(const float4*)(g_pq + ((size_t)s * BB + b) * HD + t * 4);
        acc.x += v.x; acc.y += v.y; acc.z += v.z; acc.w += v.w;
    }
    *(float4*)(g_q + (size_t)b * HD + t * 4) = acc;
    float4 ba = *(const float4*)(b_attn + t * 4);
    float4 hv = *(const float4*)(g_h1 + (size_t)b * HD + t * 4);
    float p = ba.x * hv.x + ba.y * hv.y + ba.z * hv.z + ba.w * hv.w;
    p = blockReduceSum256(p);
    if (t == 0) g_cb[b] = p;
}

// ---------------- 6: attention chunk: smem-staged scores + partial ctx ----------------
__global__ __launch_bounds__(256) void k_scores_ctx(const float* __restrict__ enc) {
    extern __shared__ float sm[];
    float* qs = sm;
    float* es = sm + 1024;
    float* ps = sm + 1024 + 16 * 1028;
    int b = blockIdx.y, ch = blockIdx.x;
    int s0 = ch * SC;
    int t = threadIdx.x;
    ((float4*)qs)[t] = ((const float4*)(g_q + (size_t)b * HD))[t];
    const float4* eb = (const float4*)(enc + ((size_t)b * SS + s0) * HD);
    #pragma unroll
    for (int r = 0; r < 16; r++) {
        int i = r * 256 + t;
        int row = i >> 8, col = i & 255;
        ((float4*)es)[row * 257 + col] = eb[i];
    }
    __syncthreads();
    int w = t >> 5, lane = t & 31;
    float cb = g_cb[b];
    unsigned long long qr[16];
    #pragma unroll
    for (int i = 0; i < 8; i++) {
        ulonglong2 qq = *(const ulonglong2*)&qs[(lane + i * 32) * 4];
        qr[2 * i] = qq.x; qr[2 * i + 1] = qq.y;
    }
    #pragma unroll
    for (int rr = 0; rr < 2; rr++) {
        int r = w * 2 + rr;
        const float* e = es + r * 1028;
        unsigned long long a0 = 0ull, a1 = 0ull;
        #pragma unroll
        for (int i = 0; i < 8; i++) {
            ulonglong2 ee = *(const ulonglong2*)&e[(lane + i * 32) * 4];
            asm("fma.rn.f32x2 %0, %1, %2, %0;" : "+l"(a0) : "l"(ee.x), "l"(qr[2 * i]));
            asm("fma.rn.f32x2 %0, %1, %2, %0;" : "+l"(a1) : "l"(ee.y), "l"(qr[2 * i + 1]));
        }
        float l0, h0_, l1, h1_;
        asm("mov.b64 {%0, %1}, %2;" : "=f"(l0), "=f"(h0_) : "l"(a0));
        asm("mov.b64 {%0, %1}, %2;" : "=f"(l1), "=f"(h1_) : "l"(a1));
        float sum = (l0 + h0_) + (l1 + h1_);
        #pragma unroll
        for (int o = 16; o > 0; o >>= 1) sum += __shfl_xor_sync(0xffffffffu, sum, o);
        if (lane == 0) {
            float val = sum + cb;
            ps[r] = val;
            g_scores[(size_t)b * SS + s0 + r] = val;
        }
    }
    __syncthreads();
    if (t < 32) {
        float v = (t < SC) ? ps[t] : -3.0e38f;
        float m = v;
        #pragma unroll
        for (int o = 16; o > 0; o >>= 1) m = fmaxf(m, __shfl_xor_sync(0xffffffffu, m, o));
        float p = (t < SC) ? expf(v - m) : 0.0f;
        float l = p;
        #pragma unroll
        for (int o = 16; o > 0; o >>= 1) l += __shfl_xor_sync(0xffffffffu, l, o);
        if (t < SC) ps[t] = p;
        if (t == 0) { g_pm[b * NCH + ch] = m; g_pl[b * NCH + ch] = l; }
    }
    __syncthreads();
    float4 acc = {0, 0, 0, 0};
    #pragma unroll
    for (int s = 0; s < SC; s++) {
        float p = ps[s];
        float4 ev = ((const float4*)es)[s * 257 + t];
        acc.x += p * ev.x; acc.y += p * ev.y; acc.z += p * ev.z; acc.w += p * ev.w;
    }
    *(float4*)(g_pctx + ((size_t)(b * NCH + ch)) * HD + t * 4) = acc;
}

// ---------------- 7: fused attn finalize: stats + ctx reduce + attn weights ----------------
// grid dim3(BB, 16): g<8 -> ctx-reduce role, g>=8 -> attn-weight role.
__global__ __launch_bounds__(256) void k_act(float* __restrict__ ctx_out,
                                             float* __restrict__ attn_out) {
    int b = blockIdx.x, g = blockIdx.y;
    int t = threadIdx.x;
    __shared__ float spm[NCH], swc[NCH];
    __shared__ float sMZ[2];
    if (t < NCH) { spm[t] = g_pm[b * NCH + t]; swc[t] = g_pl[b * NCH + t]; }
    __syncthreads();
    if (t < 32) {
        float m = -3.0e38f, z = 0.0f;
        #pragma unroll
        for (int j = 0; j < 4; j++) {
            float mv = spm[t * 4 + j], lv = swc[t * 4 + j];
            float M = fmaxf(m, mv);
            z = z * expf(m - M) + lv * expf(mv - M);
            m = M;
        }
        #pragma unroll
        for (int o = 16; o > 0; o >>= 1) {
            float mo = __shfl_xor_sync(0xffffffffu, m, o);
            float zo = __shfl_xor_sync(0xffffffffu, z, o);
            float M = fmaxf(m, mo);
            z = z * expf(m - M) + zo * expf(mo - M);
            m = M;
        }
        if (t == 0) { sMZ[0] = m; sMZ[1] = z; }
    }
    __syncthreads();
    float M = sMZ[0];
    float invZ = 1.0f / sMZ[1];
    if (g >= 8) {
        int s = (g - 8) * 256 + t;
        attn_out[(size_t)b * SS + s] = expf(g_scores[(size_t)b * SS + s] - M) * invZ;
        return;
    }
    if (t < NCH) swc[t] = expf(spm[t] - M) * invZ;
    __syncthreads();
    int cg = t >> 5, i = t & 31;
    int f4c = g * 32 + i;
    float4 acc = {0, 0, 0, 0};
    #pragma unroll
    for (int c = cg; c < NCH; c += 8) {
        float s = swc[c];
        float4 v = *(const float4*)(g_pctx + ((size_t)(b * NCH + c)) * HD + f4c * 4);
        acc.x += s * v.x; acc.y += s * v.y; acc.z += s * v.z; acc.w += s * v.w;
    }
    __shared__ float4 red[8][32];
    red[cg][i] = acc;
    __syncthreads();
    if (cg == 0) {
        #pragma unroll
        for (int r = 1; r < 8; r++) {
            float4 v = red[r][i];
            acc.x += v.x; acc.y += v.y; acc.z += v.z; acc.w += v.w;
        }
        int h = f4c * 4;
        *(float4*)(ctx_out + (size_t)b * HD + h) = acc;
        g_catT[XBLK(HD + h + 0, b)] = acc.x;
        g_catT[XBLK(HD + h + 1, b)] = acc.y;
        g_catT[XBLK(HD + h + 2, b)] = acc.z;
        g_catT[XBLK(HD + h + 3, b)] = acc.w;
    }
}

// ---------------- 8: combine logits partials + per-block softmax stats ----------------
__global__ __launch_bounds__(256) void k_lcombine() {
    int b = blockIdx.x, y = blockIdx.y;       // 8 segments of 1000 float4 per batch
    int t = threadIdx.x;
    size_t base4 = (size_t)b * (VV / 4) + (size_t)y * 1000;
    float m = -3.0e38f, s = 0.0f;
    for (int i = t; i < 1000; i += 256) {
        size_t i4 = base4 + i;
        float4 a = *(const float4*)(g_plog + i4 * 4);
        #pragma unroll
        for (int sk = 1; sk < SKL; sk++) {
            float4 v = *(const float4*)(g_plog + (size_t)sk * BB * VV + i4 * 4);
            a.x += v.x; a.y += v.y; a.z += v.z; a.w += v.w;
        }
        *(float4*)(g_logits + i4 * 4) = a;
        float m2 = fmaxf(fmaxf(a.x, a.y), fmaxf(a.z, a.w));
        if (m2 <= m) {
            s += expf(a.x - m) + expf(a.y - m) + expf(a.z - m) + expf(a.w - m);
        } else {
            s = s * expf(m - m2) + expf(a.x - m2) + expf(a.y - m2) + expf(a.z - m2) + expf(a.w - m2);
            m = m2;
        }
    }
    int lane = t & 31, w = t >> 5;
    #pragma unroll
    for (int o = 16; o > 0; o >>= 1) {
        float mo = __shfl_xor_sync(0xffffffffu, m, o);
        float so = __shfl_xor_sync(0xffffffffu, s, o);
        float M = fmaxf(m, mo);
        s = s * expf(m - M) + so * expf(mo - M);
        m = M;
    }
    __shared__ float sm_[8], ss_[8];
    if (lane == 0) { sm_[w] = m; ss_[w] = s; }
    __syncthreads();
    if (t == 0) {
        float M = sm_[0], S = ss_[0];
        #pragma unroll
        for (int i = 1; i < 8; i++) {
            float M2 = fmaxf(M, sm_[i]);
            S = S * expf(M - M2) + ss_[i] * expf(sm_[i] - M2);
            M = M2;
        }
        g_plm[b * 8 + y] = M; g_pls[b * 8 + y] = S;
    }
}

// ---------------- 9: write output softmax (inline partial-stat merge) ----------------
__global__ void k_wout(float* __restrict__ out) {
    int i4 = blockIdx.x * 256 + threadIdx.x;
    int idx = i4 * 4;
    int b = idx / VV;
    float m = g_plm[b * 8], s = g_pls[b * 8];
    #pragma unroll
    for (int j = 1; j < 8; j++) {
        float mv = g_plm[b * 8 + j], lv = g_pls[b * 8 + j];
        float M = fmaxf(m, mv);
        s = s * expf(m - M) + lv * expf(mv - M);
        m = M;
    }
    float invZ = 1.0f / s;
    float4 l = *(const float4*)(g_logits + idx);
    float4 o;
    o.x = expf(l.x - m) * invZ; o.y = expf(l.y - m) * invZ;
    o.z = expf(l.z - m) * invZ; o.w = expf(l.w - m) * invZ;
    *(float4*)(out + idx) = o;
}

// ---------------- launch ----------------
extern "C" void kernel_launch(void* const* d_in, const int* in_sizes, int n_in,
                              void* d_out, int out_size) {
    const int*   ids   = (const int*)d_in[0];
    const float* lctx  = (const float*)d_in[1];
    const float* hid   = (const float*)d_in[2];
    const float* enc   = (const float*)d_in[3];
    const float* emb   = (const float*)d_in[4];
    const float* Wattn = (const float*)d_in[5];
    const float* battn = (const float*)d_in[6];
    const float* Wih0  = (const float*)d_in[7];
    const float* Whh0  = (const float*)d_in[8];
    const float* bih0  = (const float*)d_in[9];
    const float* bhh0  = (const float*)d_in[10];
    const float* Wih1  = (const float*)d_in[11];
    const float* Whh1  = (const float*)d_in[12];
    const float* bih1  = (const float*)d_in[13];
    const float* bhh1  = (const float*)d_in[14];
    const float* Wout  = (const float*)d_in[15];
    const float* bout  = (const float*)d_in[16];

    float* out = (float*)d_out;
    float* out_probs = out;
    float* out_ctx   = out + (size_t)BB * VV;
    float* out_hid   = out_ctx + (size_t)BB * HD;
    float* out_attn  = out_hid + (size_t)2 * BB * HD;

    float *p_xT, *p_hT, *p_h0T, *p_h1, *p_h1T, *p_catT, *p_pgi, *p_pgh, *p_pq, *p_plog;
    cudaGetSymbolAddress((void**)&p_xT,   g_xT);
    cudaGetSymbolAddress((void**)&p_hT,   g_hT);
    cudaGetSymbolAddress((void**)&p_h0T,  g_h0T);
    cudaGetSymbolAddress((void**)&p_h1,   g_h1);
    cudaGetSymbolAddress((void**)&p_h1T,  g_h1T);
    cudaGetSymbolAddress((void**)&p_catT, g_catT);
    cudaGetSymbolAddress((void**)&p_pgi,  g_pgi);
    cudaGetSymbolAddress((void**)&p_pgh,  g_pgh);
    cudaGetSymbolAddress((void**)&p_pq,   g_pq);
    cudaGetSymbolAddress((void**)&p_plog, g_plog);

    const int ATTN_SMEM  = (1024 + 16 * 1028 + 16) * 4;   // 69952 B
    const int GEMMA_SMEM = 2 * STG_F * 4;                 // 82944 B
    static int init_done = 0;
    if (!init_done) {
        cudaFuncSetAttribute(k_scores_ctx, cudaFuncAttributeMaxDynamicSharedMemorySize, ATTN_SMEM);
        cudaFuncSetAttribute(k_gemmA, cudaFuncAttributeMaxDynamicSharedMemorySize, GEMMA_SMEM);
        init_done = 1;
    }

    // 1. inputs -> blocked layouts
    k_embed<<<BB, 256>>>(ids, emb, lctx);
    k_transpose<<<dim3(HD / 32, 2), dim3(32, 32)>>>(hid);
    // 2. GRU layer 0 (async dual GEMM)
    k_gemmA<<<dim3(G3/128, SK, 2), 128, GEMMA_SMEM>>>(
        p_xT, Wih0, p_pgi, (2*HD)/SK, 2*HD,
        p_hT, Whh0, p_pgh, HD/SK, HD, nullptr, G3);
    k_combine<<<256, 256>>>(bih0, bhh0, hid, p_h0T, out_hid, nullptr, nullptr);
    // 3. GRU layer 1
    k_gemmA<<<dim3(G3/128, SK, 2), 128, GEMMA_SMEM>>>(
        p_h0T, Wih1, p_pgi, HD/SK, HD,
        p_hT + HD*BB, Whh1, p_pgh, HD/SK, HD, nullptr, G3);
    k_combine<<<256, 256>>>(bih1, bhh1, hid + BB*HD, p_h1T, out_hid + BB*HD, p_h1, p_catT);
    // 4. q = h1 @ W_attn (sync GEMM, transposed W)
    k_gemm<<<dim3(HD/128, SK), 128>>>(p_h1T, Wattn, p_pq, HD/SK, HD, HD);
    k_qfin<<<BB, 256>>>(battn);
    // 5. attention: scores + fused finalize (stats/ctx/weights in one launch)
    k_scores_ctx<<<dim3(NCH, BB), 256, ATTN_SMEM>>>(enc);
    k_act<<<dim3(BB, 16), 256>>>(out_ctx, out_attn);
    // 6. logits GEMM (async, k-split x4) + fused epilogue
    k_gemmA<<<dim3(VV/128, SKL, 1), 128, GEMMA_SMEM>>>(
        p_catT, Wout, p_plog, (2*HD)/SKL, 2*HD,
        p_catT, Wout, p_plog, (2*HD)/SKL, 2*HD, bout, VV);
    k_lcombine<<<dim3(BB, 8), 256>>>();
    k_wout<<<(BB*VV/4)/256, 256>>>(out_probs);
}